// round 3
// baseline (speedup 1.0000x reference)
#include <cuda_runtime.h>
#include <cstdint>

#define NROWS 8192
#define DIM 128

// Static scratch (allocation-free per harness rules)
__device__ float g_dis[NROWS];                // rsqrt(rowsum(A)+1)
__device__ float g_z[(size_t)NROWS * DIM];    // G[j][n] = dis_j * (X W^T)[j][n], tf32-rounded

static __device__ __forceinline__ uint32_t s2u(const void* p) {
    uint32_t a;
    asm("{ .reg .u64 t; cvta.to.shared.u64 t, %1; cvt.u32.u64 %0, t; }" : "=r"(a) : "l"(p));
    return a;
}

// ===================== kernel 1: row sums -> dis =====================
__global__ void __launch_bounds__(256) rowsum_kernel(const float4* __restrict__ A4) {
    int row = blockIdx.x;
    const float4* r = A4 + (size_t)row * (NROWS / 4);
    float s = 0.f;
    #pragma unroll
    for (int p = 0; p < 8; p++) {
        float4 v = __ldcs(r + threadIdx.x + p * 256);   // streaming: don't pollute L2
        s += (v.x + v.y) + (v.z + v.w);
    }
    #pragma unroll
    for (int o = 16; o; o >>= 1) s += __shfl_xor_sync(0xffffffffu, s, o);
    __shared__ float ws[8];
    if ((threadIdx.x & 31) == 0) ws[threadIdx.x >> 5] = s;
    __syncthreads();
    if (threadIdx.x < 8) {
        float t = ws[threadIdx.x];
        #pragma unroll
        for (int o = 4; o; o >>= 1) t += __shfl_xor_sync(0xffu, t, o);
        if (threadIdx.x == 0) g_dis[row] = rsqrtf(t + 1.0f);
    }
}

// ===================== kernel 2: G[j][n] = dis_j * (X W^T), tf32-rounded =====================
__global__ void __launch_bounds__(256) z_kernel(const float* __restrict__ X,
                                                const float* __restrict__ W) {
    __shared__ float4 Xs4[32 * 32];
    int tid = threadIdx.x;
    int j0 = blockIdx.x * 32;
    const float4* Xg = reinterpret_cast<const float4*>(X) + (size_t)j0 * 32;
    for (int i = tid; i < 1024; i += 256) Xs4[i] = Xg[i];
    __syncthreads();

    int n = tid & 127, half = tid >> 7;
    float acc[16];
    #pragma unroll
    for (int jj = 0; jj < 16; jj++) acc[jj] = 0.f;

    const float4* Wr = reinterpret_cast<const float4*>(W) + (size_t)n * 32;
    #pragma unroll 4
    for (int c4 = 0; c4 < 32; c4++) {
        float4 w = __ldg(Wr + c4);
        #pragma unroll
        for (int jj = 0; jj < 16; jj++) {
            float4 x = Xs4[(half * 16 + jj) * 32 + c4];
            acc[jj] += x.x * w.x + x.y * w.y + x.z * w.z + x.w * w.w;
        }
    }
    #pragma unroll
    for (int jj = 0; jj < 16; jj++) {
        int j = j0 + half * 16 + jj;
        float z = g_dis[j] * acc[jj];
        unsigned zb;
        asm("cvt.rna.tf32.f32 %0, %1;" : "=r"(zb) : "f"(z));
        g_z[(size_t)j * DIM + n] = __uint_as_float(zb);
    }
}

// ===================== kernel 3: fused GEMM: out = dis .* (A @ G + G) + b =====================
#define BK 32
#define STG 4
#define ASTR 36                      // padded floats per A-tile row (conflict-free frags)
#define BSTR 136                     // padded floats per B-tile row
#define ASTG (128 * ASTR)            // floats per A stage
#define BSTG (BK * BSTR)             // floats per B stage
#define SMEM_BYTES (STG * (ASTG + BSTG) * 4)

static __device__ __forceinline__ void mma_tf32(float* c, const uint32_t* a, const uint32_t* b) {
    asm volatile(
        "mma.sync.aligned.m16n8k8.row.col.f32.tf32.tf32.f32 "
        "{%0,%1,%2,%3}, {%4,%5,%6,%7}, {%8,%9}, {%0,%1,%2,%3};"
        : "+f"(c[0]), "+f"(c[1]), "+f"(c[2]), "+f"(c[3])
        : "r"(a[0]), "r"(a[1]), "r"(a[2]), "r"(a[3]), "r"(b[0]), "r"(b[1]));
}

__global__ void __launch_bounds__(256) gemm_kernel(const float* __restrict__ A,
                                                   const float* __restrict__ bias,
                                                   float* __restrict__ out) {
    extern __shared__ float sm[];
    float* sA = sm;                  // [STG][ASTG]
    float* sB = sm + STG * ASTG;     // [STG][BSTG]
    const float* Bm = g_z;

    int tid = threadIdx.x, wid = tid >> 5, lane = tid & 31;
    int gid = lane >> 2, tig = lane & 3;
    const int m0 = blockIdx.x * 128;

    float acc[2][8][4];
    #pragma unroll
    for (int mf = 0; mf < 2; mf++)
        #pragma unroll
        for (int nf = 0; nf < 8; nf++)
            #pragma unroll
            for (int q = 0; q < 4; q++) acc[mf][nf][q] = 0.f;

    // 8 warps: 4 row-groups x 2 col-groups; warp tile 32x64
    const int wm0 = (wid >> 1) * 32, wn0 = (wid & 1) * 64;

    // async-copy one stage (A 128xBK streaming, B BKx128), 4+4 float4 per thread
    auto issue = [&](int stage, int buf) {
        int kk = stage * BK;
        #pragma unroll
        for (int it = 0; it < 4; it++) {
            int idx = it * 256 + tid;
            int r = idx >> 3, c4 = idx & 7;
            const float* gp = A + (size_t)(m0 + r) * NROWS + kk + c4 * 4;
            uint32_t sa = s2u(sA + buf * ASTG + r * ASTR + c4 * 4);
            asm volatile("cp.async.cg.shared.global [%0], [%1], 16;" :: "r"(sa), "l"(gp));
        }
        #pragma unroll
        for (int it = 0; it < 4; it++) {
            int idx = it * 256 + tid;
            int r = idx >> 5, c4 = idx & 31;
            const float* gp = Bm + (size_t)(kk + r) * DIM + c4 * 4;
            uint32_t sb = s2u(sB + buf * BSTG + r * BSTR + c4 * 4);
            asm volatile("cp.async.cg.shared.global [%0], [%1], 16;" :: "r"(sb), "l"(gp));
        }
        asm volatile("cp.async.commit_group;");
    };

    #pragma unroll
    for (int s = 0; s < STG - 1; s++) issue(s, s);

    const int NS = NROWS / BK;  // 256
    for (int i = 0; i < NS; i++) {
        asm volatile("cp.async.wait_group %0;" :: "n"(STG - 2));
        __syncthreads();
        if (i + STG - 1 < NS) issue(i + STG - 1, (i + STG - 1) & (STG - 1));

        const float* a_s = sA + (i & (STG - 1)) * ASTG;
        const float* b_s = sB + (i & (STG - 1)) * BSTG;

        #pragma unroll
        for (int ks = 0; ks < BK / 8; ks++) {
            int k0 = ks * 8;
            uint32_t ar[2][4], br[8][2];
            #pragma unroll
            for (int mf = 0; mf < 2; mf++) {
                const float* p = a_s + (wm0 + mf * 16 + gid) * ASTR + k0 + tig;
                ar[mf][0] = __float_as_uint(p[0]);
                ar[mf][1] = __float_as_uint(p[8 * ASTR]);
                ar[mf][2] = __float_as_uint(p[4]);
                ar[mf][3] = __float_as_uint(p[8 * ASTR + 4]);
            }
            #pragma unroll
            for (int nf = 0; nf < 8; nf++) {
                const float* p = b_s + (k0 + tig) * BSTR + wn0 + nf * 8 + gid;
                br[nf][0] = __float_as_uint(p[0]);
                br[nf][1] = __float_as_uint(p[4 * BSTR]);
            }
            #pragma unroll
            for (int mf = 0; mf < 2; mf++)
                #pragma unroll
                for (int nf = 0; nf < 8; nf++)
                    mma_tf32(acc[mf][nf], ar[mf], br[nf]);
        }
    }

    // fused epilogue: out = dis .* (acc + G) + bias
    #pragma unroll
    for (int mf = 0; mf < 2; mf++) {
        int r0 = m0 + wm0 + mf * 16 + gid;
        float d0 = g_dis[r0], d1 = g_dis[r0 + 8];
        #pragma unroll
        for (int nf = 0; nf < 8; nf++) {
            int c = wn0 + nf * 8 + 2 * tig;
            float2 bb = __ldg(reinterpret_cast<const float2*>(bias + c));
            float2 gz0 = *reinterpret_cast<const float2*>(&g_z[(size_t)r0 * DIM + c]);
            float2 gz1 = *reinterpret_cast<const float2*>(&g_z[(size_t)(r0 + 8) * DIM + c]);
            float2 o0, o1;
            o0.x = d0 * (acc[mf][nf][0] + gz0.x) + bb.x;
            o0.y = d0 * (acc[mf][nf][1] + gz0.y) + bb.y;
            o1.x = d1 * (acc[mf][nf][2] + gz1.x) + bb.x;
            o1.y = d1 * (acc[mf][nf][3] + gz1.y) + bb.y;
            *reinterpret_cast<float2*>(&out[(size_t)r0 * DIM + c]) = o0;
            *reinterpret_cast<float2*>(&out[(size_t)(r0 + 8) * DIM + c]) = o1;
        }
    }
}

// ===================== host =====================
extern "C" void kernel_launch(void* const* d_in, const int* in_sizes, int n_in,
                              void* d_out, int out_size) {
    const float* X = (const float*)d_in[0];
    const float* A = (const float*)d_in[1];
    const float* W = (const float*)d_in[2];
    const float* b = (const float*)d_in[3];
    float* out = (float*)d_out;

    rowsum_kernel<<<NROWS, 256>>>((const float4*)A);
    z_kernel<<<NROWS / 32, 256>>>(X, W);

    cudaFuncSetAttribute(gemm_kernel, cudaFuncAttributeMaxDynamicSharedMemorySize, SMEM_BYTES);
    gemm_kernel<<<NROWS / 128, 256, SMEM_BYTES>>>(A, b, out);
}

// round 4
// speedup vs baseline: 1.3661x; 1.3661x over previous
#include <cuda_runtime.h>
#include <cstdint>

#define NROWS 8192
#define DIM 128

// Static scratch (allocation-free per harness rules)
__device__ float g_dis[NROWS];                 // rsqrt(rowsum(A)+1)
__device__ float g_zt[(size_t)DIM * NROWS];    // G^T[n][j] = dis_j*(X W^T)[j][n], tf32-rounded

static __device__ __forceinline__ uint32_t s2u(const void* p) {
    uint32_t a;
    asm("{ .reg .u64 t; cvta.to.shared.u64 t, %1; cvt.u32.u64 %0, t; }" : "=r"(a) : "l"(p));
    return a;
}

// ===================== kernel 1: row sums -> dis =====================
__global__ void __launch_bounds__(256) rowsum_kernel(const float4* __restrict__ A4) {
    int row = blockIdx.x;
    const float4* r = A4 + (size_t)row * (NROWS / 4);
    float s = 0.f;
    #pragma unroll
    for (int p = 0; p < 8; p++) {
        float4 v = __ldcs(r + threadIdx.x + p * 256);
        s += (v.x + v.y) + (v.z + v.w);
    }
    #pragma unroll
    for (int o = 16; o; o >>= 1) s += __shfl_xor_sync(0xffffffffu, s, o);
    __shared__ float ws[8];
    if ((threadIdx.x & 31) == 0) ws[threadIdx.x >> 5] = s;
    __syncthreads();
    if (threadIdx.x < 8) {
        float t = ws[threadIdx.x];
        #pragma unroll
        for (int o = 4; o; o >>= 1) t += __shfl_xor_sync(0xffu, t, o);
        if (threadIdx.x == 0) g_dis[row] = rsqrtf(t + 1.0f);
    }
}

// ===================== kernel 2: G^T[n][j] = dis_j*(X W^T)[j][n], tf32-rounded =====================
__global__ void __launch_bounds__(256) z_kernel(const float* __restrict__ X,
                                                const float* __restrict__ W) {
    __shared__ float4 Xs4[32 * 32];       // 32 rows x 128 floats
    __shared__ float T[128][33];          // transpose staging (pad 33: conflict-free)
    int tid = threadIdx.x;
    int j0 = blockIdx.x * 32;
    const float4* Xg = reinterpret_cast<const float4*>(X) + (size_t)j0 * 32;
    for (int i = tid; i < 1024; i += 256) Xs4[i] = Xg[i];
    __syncthreads();

    int n = tid & 127, half = tid >> 7;
    float acc[16];
    #pragma unroll
    for (int jj = 0; jj < 16; jj++) acc[jj] = 0.f;

    const float4* Wr = reinterpret_cast<const float4*>(W) + (size_t)n * 32;
    #pragma unroll 4
    for (int c4 = 0; c4 < 32; c4++) {
        float4 w = __ldg(Wr + c4);
        #pragma unroll
        for (int jj = 0; jj < 16; jj++) {
            float4 x = Xs4[(half * 16 + jj) * 32 + c4];
            acc[jj] += x.x * w.x + x.y * w.y + x.z * w.z + x.w * w.w;
        }
    }
    #pragma unroll
    for (int jj = 0; jj < 16; jj++) {
        int j = j0 + half * 16 + jj;
        float z = g_dis[j] * acc[jj];
        unsigned zb;
        asm("cvt.rna.tf32.f32 %0, %1;" : "=r"(zb) : "f"(z));
        T[n][half * 16 + jj] = __uint_as_float(zb);
    }
    __syncthreads();
    // coalesced store: 128 n-rows x 32 j each; 4 float4 per thread
    #pragma unroll
    for (int it = 0; it < 4; it++) {
        int idx = it * 256 + tid;            // 0..1023 float4 slots
        int nn = idx >> 3, j4 = idx & 7;
        float4 v = make_float4(T[nn][j4 * 4], T[nn][j4 * 4 + 1], T[nn][j4 * 4 + 2], T[nn][j4 * 4 + 3]);
        *reinterpret_cast<float4*>(&g_zt[(size_t)nn * NROWS + j0 + j4 * 4]) = v;
    }
}

// ===================== kernel 3: fused GEMM: out = dis .* (A @ G + G) + b =====================
#define BM 64
#define BK 32
#define STG 4
#define ASTR 36                       // padded row stride (floats); 4m mod 32 spans all groups
#define BSTR 36
#define ASTG (BM * ASTR)              // 2304 floats
#define BSTG (DIM * BSTR)             // 4608 floats
#define SMEM_BYTES (STG * (ASTG + BSTG) * 4)   // 110592 B

static __device__ __forceinline__ void mma_tf32(float* c, const uint32_t* a, const uint32_t* b) {
    asm volatile(
        "mma.sync.aligned.m16n8k8.row.col.f32.tf32.tf32.f32 "
        "{%0,%1,%2,%3}, {%4,%5,%6,%7}, {%8,%9}, {%0,%1,%2,%3};"
        : "+f"(c[0]), "+f"(c[1]), "+f"(c[2]), "+f"(c[3])
        : "r"(a[0]), "r"(a[1]), "r"(a[2]), "r"(a[3]), "r"(b[0]), "r"(b[1]));
}

static __device__ __forceinline__ void ldsm4(uint32_t* r, uint32_t addr) {
    asm volatile("ldmatrix.sync.aligned.m8n8.x4.shared.b16 {%0,%1,%2,%3}, [%4];"
                 : "=r"(r[0]), "=r"(r[1]), "=r"(r[2]), "=r"(r[3]) : "r"(addr));
}

__global__ void __launch_bounds__(128) gemm_kernel(const float* __restrict__ A,
                                                   const float* __restrict__ bias,
                                                   float* __restrict__ out) {
    extern __shared__ float sm[];
    float* sA = sm;                   // [STG][ASTG] k-major rows of m
    float* sB = sm + STG * ASTG;      // [STG][BSTG] k-major rows of n (g_zt layout)

    int tid = threadIdx.x, wid = tid >> 5, lane = tid & 31;
    int gid = lane >> 2, tig = lane & 3;
    const int m0 = blockIdx.x * BM;

    float acc[2][8][4];
    #pragma unroll
    for (int mf = 0; mf < 2; mf++)
        #pragma unroll
        for (int nf = 0; nf < 8; nf++)
            #pragma unroll
            for (int q = 0; q < 4; q++) acc[mf][nf][q] = 0.f;

    // 4 warps: 2 m-groups x 2 n-groups; warp tile 32x64
    const int wm0 = (wid >> 1) * 32, wn0 = (wid & 1) * 64;

    // ldmatrix per-lane row selectors
    const int lrow = lane & 15;            // row within 16 (m or n)
    const int ksel = (lane >> 4) * 4;      // k sub-offset 0 or 4

    auto issue = [&](int stage, int buf) {
        int kk = stage * BK;
        #pragma unroll
        for (int it = 0; it < 4; it++) {               // A: 64 rows x 8 chunks = 512
            int idx = it * 128 + tid;
            int r = idx >> 3, c4 = idx & 7;
            const float* gp = A + (size_t)(m0 + r) * NROWS + kk + c4 * 4;
            uint32_t sa = s2u(sA + buf * ASTG + r * ASTR + c4 * 4);
            asm volatile("cp.async.cg.shared.global [%0], [%1], 16;" :: "r"(sa), "l"(gp));
        }
        #pragma unroll
        for (int it = 0; it < 8; it++) {               // B: 128 n-rows x 8 chunks = 1024
            int idx = it * 128 + tid;
            int r = idx >> 3, c4 = idx & 7;
            const float* gp = g_zt + (size_t)r * NROWS + kk + c4 * 4;
            uint32_t sb = s2u(sB + buf * BSTG + r * BSTR + c4 * 4);
            asm volatile("cp.async.cg.shared.global [%0], [%1], 16;" :: "r"(sb), "l"(gp));
        }
        asm volatile("cp.async.commit_group;");
    };

    #pragma unroll
    for (int s = 0; s < STG - 1; s++) issue(s, s);

    const int NS = NROWS / BK;  // 256
    for (int i = 0; i < NS; i++) {
        asm volatile("cp.async.wait_group %0;" :: "n"(STG - 2));
        __syncthreads();
        if (i + STG - 1 < NS) issue(i + STG - 1, (i + STG - 1) & (STG - 1));

        uint32_t a_s = s2u(sA + (i & (STG - 1)) * ASTG);
        uint32_t b_s = s2u(sB + (i & (STG - 1)) * BSTG);

        #pragma unroll
        for (int ks = 0; ks < BK / 8; ks++) {
            int k0 = ks * 8;
            uint32_t ar[2][4], br[4][4];
            #pragma unroll
            for (int mf = 0; mf < 2; mf++)            // A 16x8 tiles via ldmatrix.x4
                ldsm4(ar[mf], a_s + 4u * ((wm0 + mf * 16 + lrow) * ASTR + k0 + ksel));
            #pragma unroll
            for (int p = 0; p < 4; p++)               // B: two n8-tiles per ldmatrix.x4
                ldsm4(br[p], b_s + 4u * ((wn0 + p * 16 + lrow) * BSTR + k0 + ksel));
            #pragma unroll
            for (int mf = 0; mf < 2; mf++)
                #pragma unroll
                for (int p = 0; p < 4; p++) {
                    // br[p] = {b0(nf=2p), b0(nf=2p+1), b1(nf=2p), b1(nf=2p+1)}
                    uint32_t b0[2] = {br[p][0], br[p][2]};
                    uint32_t b1[2] = {br[p][1], br[p][3]};
                    mma_tf32(acc[mf][2 * p], ar[mf], b0);
                    mma_tf32(acc[mf][2 * p + 1], ar[mf], b1);
                }
        }
    }

    // fused epilogue: out = dis .* (acc + G) + bias   (G read from g_zt, L2-resident)
    #pragma unroll
    for (int mf = 0; mf < 2; mf++) {
        int r0 = m0 + wm0 + mf * 16 + gid;
        float d0 = g_dis[r0], d1 = g_dis[r0 + 8];
        #pragma unroll
        for (int nf = 0; nf < 8; nf++) {
            int c = wn0 + nf * 8 + 2 * tig;
            float2 bb = __ldg(reinterpret_cast<const float2*>(bias + c));
            float gz00 = g_zt[(size_t)c * NROWS + r0];
            float gz01 = g_zt[(size_t)(c + 1) * NROWS + r0];
            float gz10 = g_zt[(size_t)c * NROWS + r0 + 8];
            float gz11 = g_zt[(size_t)(c + 1) * NROWS + r0 + 8];
            float2 o0, o1;
            o0.x = d0 * (acc[mf][nf][0] + gz00) + bb.x;
            o0.y = d0 * (acc[mf][nf][1] + gz01) + bb.y;
            o1.x = d1 * (acc[mf][nf][2] + gz10) + bb.x;
            o1.y = d1 * (acc[mf][nf][3] + gz11) + bb.y;
            *reinterpret_cast<float2*>(&out[(size_t)r0 * DIM + c]) = o0;
            *reinterpret_cast<float2*>(&out[(size_t)(r0 + 8) * DIM + c]) = o1;
        }
    }
}

// ===================== host =====================
extern "C" void kernel_launch(void* const* d_in, const int* in_sizes, int n_in,
                              void* d_out, int out_size) {
    const float* X = (const float*)d_in[0];
    const float* A = (const float*)d_in[1];
    const float* W = (const float*)d_in[2];
    const float* b = (const float*)d_in[3];
    float* out = (float*)d_out;

    rowsum_kernel<<<NROWS, 256>>>((const float4*)A);
    z_kernel<<<NROWS / 32, 256>>>(X, W);

    cudaFuncSetAttribute(gemm_kernel, cudaFuncAttributeMaxDynamicSharedMemorySize, SMEM_BYTES);
    gemm_kernel<<<NROWS / BM, 128, SMEM_BYTES>>>(A, b, out);
}